// round 14
// baseline (speedup 1.0000x reference)
#include <cuda_runtime.h>
#include <math.h>

// ---------------------------------------------------------------------------
// SoftLabelLoss: loss = max( (1/B) * sum_i [ e[t_i] - dot(soft[t_i], x_i) + lse(x_i) ], 0 )
// v14 = v13 (bf16x2 table, 768x2 blocks = 48 warps/SM, unroll-2, batched lse)
//       + register-free L2 prefetch at distance 8 rows:
//       register pipeline now only covers L2-hit latency, not DRAM latency.
// ---------------------------------------------------------------------------

#define FXSCALE 4294967296.0   // 2^32

__device__ unsigned long long g_sum  = 0ULL;
__device__ unsigned int       g_done = 0u;

__device__ __forceinline__ float warp_sum_f32(float v) {
    #pragma unroll
    for (int o = 16; o; o >>= 1) v += __shfl_xor_sync(0xffffffffu, v, o);
    return v;
}

// exact bf16 -> f32 from packed bf16x2
__device__ __forceinline__ float blo(unsigned u) { return __uint_as_float(u << 16); }
__device__ __forceinline__ float bhi(unsigned u) { return __uint_as_float(u & 0xffff0000u); }
__device__ __forceinline__ unsigned pack_bf16x2(float a, float b) {
    unsigned r;
    asm("cvt.rn.bf16x2.f32 %0, %1, %2;" : "=r"(r) : "f"(b), "f"(a));  // b=hi, a=lo
    return r;
}
__device__ __forceinline__ void pf_l2(const void* p) {
    asm volatile("prefetch.global.L2 [%0];" :: "l"(p));
}

// --- deterministic fixed-point finalize -------------------------------------------
__device__ __forceinline__ void block_finalize(float acc, int lane, int warp,
                                               double* s_w, float* out, int B) {
    double d = (double)acc;
    #pragma unroll
    for (int o = 16; o; o >>= 1) d += __shfl_xor_sync(0xffffffffu, d, o);
    if (lane == 0) s_w[warp] = d;
    __syncthreads();
    if (warp == 0) {
        int nw = (blockDim.x + 31) >> 5;
        double v = (lane < nw) ? s_w[lane] : 0.0;
        #pragma unroll
        for (int o = 16; o; o >>= 1) v += __shfl_xor_sync(0xffffffffu, v, o);
        if (lane == 0) {
            long long q = __double2ll_rn(v * FXSCALE);
            atomicAdd(&g_sum, (unsigned long long)q);
            __threadfence();
            unsigned int tk = atomicAdd(&g_done, 1u);
            if (tk == gridDim.x - 1) {
                unsigned long long raw = atomicAdd(&g_sum, 0ULL);
                double loss = ((double)(long long)raw / FXSCALE) / (double)B;
                out[0] = (float)(loss > 0.0 ? loss : 0.0);
                g_sum  = 0ULL;
                g_done = 0u;
                __threadfence();
            }
        }
    }
}

// --- v14 main kernel, compile-time C (C even, 128 < C <= 172) ------------------------
template<int C>
__global__ __launch_bounds__(768, 2)
void slloss_v14(const float* __restrict__ logits,
                const int*   __restrict__ targets,
                const float* __restrict__ sim,
                float* __restrict__ out, int B) {
    constexpr int C2    = C / 2;          // 85 words per table row / float2 per logit row
    constexpr int W     = 24;             // warps per block
    constexpr int RSTR  = 36;             // se-partial row stride (floats)
    constexpr int OFF_RED = (256 + 688 + C * C2 * 4 + 15) & ~15;   // 16B aligned
    constexpr int PFD   = 8;              // prefetch distance (rows)
    static_assert((C & 1) == 0 && C2 > 64 && C2 <= 86, "tuned for 128<C<=172");

    extern __shared__ __align__(16) unsigned char smraw[];
    double*   s_w     = (double*)smraw;                             // 256 B
    float*    s_ent   = (float*)(smraw + 256);                      // C floats (pad 688)
    unsigned* s_softu = (unsigned*)(smraw + 256 + 688);             // C*C2 words
    float*    s_red   = (float*)(smraw + OFF_RED);                  // W*8*RSTR floats

    const int lane = threadIdx.x & 31;
    const int warp = threadIdx.x >> 5;

    // ---- build bf16 table + f32 entropies ----
    for (int t = warp; t < C; t += W) {
        const float* srow = sim + (size_t)t * C;
        float s = 0.0f;
        for (int c = lane; c < C; c += 32) s += __ldg(srow + c);
        s = warp_sum_f32(s);
        const float inv = 0.2f / s;
        float pe = 0.0f;
        for (int j = lane; j < C2; j += 32) {
            int c0 = 2 * j, c1 = 2 * j + 1;
            float v0 = __ldg(srow + c0) * inv + (c0 == t ? 0.8f : 0.0f);
            float v1 = __ldg(srow + c1) * inv + (c1 == t ? 0.8f : 0.0f);
            pe += (v0 > 0.0f ? v0 * __logf(v0) : 0.0f)
                + (v1 > 0.0f ? v1 * __logf(v1) : 0.0f);
            s_softu[t * C2 + j] = pack_bf16x2(v0, v1);
        }
        pe = warp_sum_f32(pe);
        if (lane == 0) s_ent[t] = pe;
    }
    __syncthreads();

    const int NW = gridDim.x * W;
    const int gw = blockIdx.x * W + warp;

    int per = (int)((((long long)B + NW - 1) / NW + 15) & ~15LL);   // mult of 16
    int r0  = gw * per;  if (r0 > B) r0 = B;
    int r1  = r0 + per;  if (r1 > B) r1 = B;
    const int n  = r1 - r0;
    const int n8 = n & ~7;

    const bool act2   = lane < (C2 - 64);     // partial third chunk (lane < 21)
    const bool lanepf = lane < ((2 * C * 4 + 127) / 128);  // 2-row pair = 1360B -> 11 lanes
    float* red = s_red + warp * (8 * RSTR);

    float accD = 0.0f;   // -dot partials (all lanes)
    float accL = 0.0f;   // ent + log(se) (lanes 0..7 in batched mode)

    if (n8 >= 8) {
        const float2* p = (const float2*)logits + (size_t)r0 * C2;
        const int* tg = targets + r0;

        int t32  = (lane      < n) ? __ldg(tg + lane)      : -1;
        int t32n = (lane + 32 < n) ? __ldg(tg + 32 + lane) : -1;

        float2 b0[3], b1[3];
        #define LD3(BUF, D)                                       \
            BUF[0] = __ldcs(p + (D) * C2 + lane);                 \
            BUF[1] = __ldcs(p + (D) * C2 + 32 + lane);            \
            if (act2) BUF[2] = __ldcs(p + (D) * C2 + 64 + lane);
        LD3(b0, 0) LD3(b1, 1)

        for (int i = 0; i < n8; i += 8) {
            if ((i & 31) == 0 && i > 0) {
                t32  = t32n;
                t32n = (i + 32 + lane < n) ? __ldg(tg + i + 32 + lane) : -1;
            }
            const int sidx = i & 31;            // 0,8,16,24

            #pragma unroll
            for (int rr = 0; rr < 8; rr += 2) {

                // register-free L2 prefetch of rows (i+rr+PFD, i+rr+PFD+1)
                if (lanepf && (i + rr + PFD + 1) < n8) {
                    pf_l2((const char*)(p + PFD * C2) + lane * 128);
                }

                #define DO_ROW(BUF, D)                                              \
                {                                                                   \
                    const bool more = (i + rr + (D) + 2) < n8;                      \
                    int t  = __shfl_sync(0xffffffffu, t32, sidx + rr + (D));        \
                    int tw = (t >= 0) ? t : 0;                                      \
                    const unsigned* swu = s_softu + tw * C2;                        \
                    float2 x0 = BUF[0], x1 = BUF[1], x2 = BUF[2];                   \
                    if (more) { LD3(BUF, (D) + 2) }                                 \
                    unsigned wu0 = swu[lane], wu1 = swu[lane + 32];                 \
                    float seA = __expf(x0.x) + __expf(x0.y);                        \
                    float seB = __expf(x1.x) + __expf(x1.y);                        \
                    float dt = 0.0f;                                                \
                    dt = fmaf(blo(wu0), x0.x, dt); dt = fmaf(bhi(wu0), x0.y, dt);   \
                    dt = fmaf(blo(wu1), x1.x, dt); dt = fmaf(bhi(wu1), x1.y, dt);   \
                    if (act2) {                                                     \
                        unsigned wu2 = swu[lane + 64];                              \
                        seA += __expf(x2.x) + __expf(x2.y);                         \
                        dt = fmaf(blo(wu2), x2.x, dt);                              \
                        dt = fmaf(bhi(wu2), x2.y, dt);                              \
                    }                                                               \
                    red[(rr + (D)) * RSTR + lane] = seA + seB;                      \
                    if (t >= 0) accD -= dt;                                         \
                }

                DO_ROW(b0, 0)
                DO_ROW(b1, 1)
                #undef DO_ROW

                p += 2 * C2;
            }

            // batched lse: lanes 0..7 each own one row of this 8-row group
            __syncwarp();
            float sum = 0.0f;
            if (lane < 8) {
                const float4* q = (const float4*)(red + lane * RSTR);
                #pragma unroll
                for (int k = 0; k < 8; k++) {
                    float4 v = q[k];
                    sum += (v.x + v.y) + (v.z + v.w);
                }
            }
            int tr = __shfl_sync(0xffffffffu, t32, (sidx + lane) & 31);
            if (lane < 8 && tr >= 0) accL += s_ent[tr] + __logf(sum);
            __syncwarp();
        }
        #undef LD3
    }

    // scalar tail (<8 rows; empty when per-warp ranges are 16-multiples)
    for (int i = n8; i < n; i++) {
        int t = __ldg(targets + r0 + i);
        const float* lg = logits + (size_t)(r0 + i) * C;
        const unsigned* swu = s_softu + ((t >= 0) ? t : 0) * C2;
        float se = 0.f, dt = 0.f;
        for (int j = lane; j < C2; j += 32) {
            float x0 = __ldg(lg + 2 * j), x1 = __ldg(lg + 2 * j + 1);
            unsigned wu = swu[j];
            se += __expf(x0) + __expf(x1);
            dt = fmaf(blo(wu), x0, dt);
            dt = fmaf(bhi(wu), x1, dt);
        }
        se = warp_sum_f32(se);
        if (t >= 0) {
            accD -= dt;
            if (lane == 0) accL += s_ent[t] + __logf(se);
        }
    }

    block_finalize(accD + accL, lane, warp, s_w, out, B);
}

// --- generic fallback (any C, f32 table) ---------------------------------------------
__global__ __launch_bounds__(1024, 1)
void slloss_fused_gen(const float* __restrict__ logits,
                      const int*   __restrict__ targets,
                      const float* __restrict__ sim,
                      float* __restrict__ out,
                      int B, int C) {
    extern __shared__ float smemf[];
    float*  s_soft = smemf;
    float*  s_ent  = smemf + C * C;
    double* s_w    = (double*)(smemf + C * C + ((C + 1) & ~1));

    const int tid = threadIdx.x, lane = tid & 31, warp = tid >> 5;
    for (int t = warp; t < C; t += 32) {
        const float* srow = sim + (size_t)t * C;
        float s = 0.0f;
        for (int c = lane; c < C; c += 32) {
            float v = __ldg(srow + c);
            s_soft[t * C + c] = v;
            s += v;
        }
        s = warp_sum_f32(s);
        float inv = 0.2f / s;
        float pe = 0.0f;
        for (int c = lane; c < C; c += 32) {
            float soft = s_soft[t * C + c] * inv + (c == t ? 0.8f : 0.0f);
            s_soft[t * C + c] = soft;
            pe += (soft > 0.0f) ? soft * __logf(soft) : 0.0f;
        }
        pe = warp_sum_f32(pe);
        if (lane == 0) s_ent[t] = pe;
    }
    __syncthreads();

    const int NW = gridDim.x * 32;
    const int gw = blockIdx.x * 32 + warp;
    long long per = ((long long)B + NW - 1) / NW;
    long long r0 = (long long)gw * per; if (r0 > B) r0 = B;
    long long r1 = r0 + per;            if (r1 > B) r1 = B;

    float acc = 0.0f;
    for (long long row = r0; row < r1; row++) {
        int t = __ldg(&targets[row]);
        if (t < 0) continue;
        const float* lg = logits + (size_t)row * C;
        const float* sw = s_soft + t * C;
        float se = 0.f, dt = 0.f;
        for (int c = lane; c < C; c += 32) {
            float x = __ldg(lg + c);
            se += __expf(x);
            dt = fmaf(sw[c], x, dt);
        }
        se = warp_sum_f32(se);
        acc -= dt;
        if (lane == 0) acc += s_ent[t] + __logf(se);
    }
    block_finalize(acc, lane, warp, s_w, out, B);
}

extern "C" void kernel_launch(void* const* d_in, const int* in_sizes, int n_in,
                              void* d_out, int out_size) {
    const float* logits  = (const float*)d_in[0];
    const int*   targets = (const int*)  d_in[1];
    const float* sim     = (const float*)d_in[2];
    float*       out     = (float*)d_out;

    int B = in_sizes[1];
    int C = in_sizes[0] / B;

    int nsm = 148;
    cudaDeviceGetAttribute(&nsm, cudaDevAttrMultiProcessorCount, 0);

    if (C == 170) {
        constexpr int Cc = 170, C2 = Cc / 2, W = 24, RSTR = 36;
        constexpr size_t OFF_RED = (256 + 688 + (size_t)Cc * C2 * 4 + 15) & ~(size_t)15;
        size_t smem = OFF_RED + (size_t)W * 8 * RSTR * 4;
        cudaFuncSetAttribute(slloss_v14<Cc>, cudaFuncAttributeMaxDynamicSharedMemorySize, (int)smem);
        slloss_v14<Cc><<<2 * nsm, 768, smem>>>(logits, targets, sim, out, B);
    } else {
        size_t smem = (size_t)(C * C + ((C + 1) & ~1)) * sizeof(float) + 32 * sizeof(double);
        cudaFuncSetAttribute(slloss_fused_gen, cudaFuncAttributeMaxDynamicSharedMemorySize, (int)smem);
        slloss_fused_gen<<<nsm, 1024, smem>>>(logits, targets, sim, out, B, C);
    }
}

// round 15
// speedup vs baseline: 1.2197x; 1.2197x over previous
#include <cuda_runtime.h>
#include <math.h>

// ---------------------------------------------------------------------------
// SoftLabelLoss: loss = max( (1/B) * sum_i [ e[t_i] - dot(soft[t_i], x_i) + lse(x_i) ], 0 )
// v15 = v10 (f32 table, unroll-4 register pipeline, 16-row batched smem lse)
//       at 768 threads x 1 block/SM: 85-reg budget eliminates the spills that
//       inflated v10's instruction stream (regs were pinned at 64).
// ---------------------------------------------------------------------------

#define FXSCALE 4294967296.0   // 2^32

__device__ unsigned long long g_sum  = 0ULL;
__device__ unsigned int       g_done = 0u;

__device__ __forceinline__ float warp_sum_f32(float v) {
    #pragma unroll
    for (int o = 16; o; o >>= 1) v += __shfl_xor_sync(0xffffffffu, v, o);
    return v;
}

// --- deterministic fixed-point finalize -------------------------------------------
__device__ __forceinline__ void block_finalize(float acc, int lane, int warp,
                                               double* s_w, float* out, int B) {
    double d = (double)acc;
    #pragma unroll
    for (int o = 16; o; o >>= 1) d += __shfl_xor_sync(0xffffffffu, d, o);
    if (lane == 0) s_w[warp] = d;
    __syncthreads();
    if (warp == 0) {
        int nw = (blockDim.x + 31) >> 5;
        double v = (lane < nw) ? s_w[lane] : 0.0;
        #pragma unroll
        for (int o = 16; o; o >>= 1) v += __shfl_xor_sync(0xffffffffu, v, o);
        if (lane == 0) {
            long long q = __double2ll_rn(v * FXSCALE);
            atomicAdd(&g_sum, (unsigned long long)q);
            __threadfence();
            unsigned int tk = atomicAdd(&g_done, 1u);
            if (tk == gridDim.x - 1) {
                unsigned long long raw = atomicAdd(&g_sum, 0ULL);
                double loss = ((double)(long long)raw / FXSCALE) / (double)B;
                out[0] = (float)(loss > 0.0 ? loss : 0.0);
                g_sum  = 0ULL;
                g_done = 0u;
                __threadfence();
            }
        }
    }
}

// --- shared f32 table build (warp-cooperative, any warp count) -----------------------
__device__ __forceinline__ void build_table(const float* __restrict__ sim,
                                            float* s_soft, float* s_ent,
                                            int C, int lane, int warp, int nwarps) {
    for (int t = warp; t < C; t += nwarps) {
        const float* srow = sim + (size_t)t * C;
        float s = 0.0f;
        for (int c = lane; c < C; c += 32) {
            float v = __ldg(srow + c);
            s_soft[t * C + c] = v;
            s += v;
        }
        s = warp_sum_f32(s);
        float inv = 0.2f / s;
        float p = 0.0f;
        for (int c = lane; c < C; c += 32) {
            float soft = s_soft[t * C + c] * inv + (c == t ? 0.8f : 0.0f);
            s_soft[t * C + c] = soft;
            p += (soft > 0.0f) ? soft * __logf(soft) : 0.0f;
        }
        p = warp_sum_f32(p);
        if (lane == 0) s_ent[t] = p;
    }
}

// --- v15 main kernel, compile-time C (C even, 128 < C <= 172) ------------------------
template<int C>
__global__ __launch_bounds__(768, 1)
void slloss_v15(const float* __restrict__ logits,
                const int*   __restrict__ targets,
                const float* __restrict__ sim,
                float* __restrict__ out, int B) {
    constexpr int C2   = C / 2;         // 85 float2 per row
    constexpr int W    = 24;            // warps per block
    constexpr int RSTR = 36;            // se-partial row stride (floats)
    static_assert((C & 1) == 0 && C2 > 64 && C2 <= 86, "tuned for 128<C<=172");

    extern __shared__ __align__(16) unsigned char smraw[];
    double* s_w    = (double*)smraw;                              // 256 B
    float*  s_ent  = (float*)(smraw + 256);                       // C floats (pad 688)
    float*  s_soft = (float*)(smraw + 256 + 688);                 // C*C floats
    float*  s_red  = (float*)(smraw + 256 + 688 + C * C * 4);     // W*16*RSTR floats

    const int lane = threadIdx.x & 31;
    const int warp = threadIdx.x >> 5;

    build_table(sim, s_soft, s_ent, C, lane, warp, W);
    __syncthreads();

    const int NW = gridDim.x * W;
    const int gw = blockIdx.x * W + warp;

    int per = (int)((((long long)B + NW - 1) / NW + 15) & ~15LL);   // mult of 16
    int r0  = gw * per;      if (r0 > B) r0 = B;
    int r1  = r0 + per;      if (r1 > B) r1 = B;
    const int n   = r1 - r0;
    const int n16 = n & ~15;

    const bool act2 = lane < (C2 - 64);       // partial third chunk (lane < 21)
    float* red = s_red + warp * (16 * RSTR);

    float accD = 0.0f;   // -dot partials (all lanes)
    float accL = 0.0f;   // ent + log(se) (lanes 0..15 in batched mode)

    int t32 = -1;

    if (n16 >= 16) {
        const float2* p = (const float2*)logits + (size_t)r0 * C2;

        float2 b0[3], b1[3], b2[3], b3[3];
        #define LD3(BUF, D)                                       \
            BUF[0] = __ldcs(p + (D) * C2 + lane);                 \
            BUF[1] = __ldcs(p + (D) * C2 + 32 + lane);            \
            if (act2) BUF[2] = __ldcs(p + (D) * C2 + 64 + lane);
        LD3(b0, 0) LD3(b1, 1) LD3(b2, 2) LD3(b3, 3)

        for (int i = 0; i < n16; i += 16) {
            const int gp = (i >> 4) & 1;
            if (gp == 0) {
                int rem = n - i;
                t32 = (lane < rem) ? __ldg(targets + r0 + i + lane) : -1;
            }
            const int sidx = gp << 4;

            #pragma unroll
            for (int rr = 0; rr < 16; rr += 4) {
                const bool more = (i + rr + 4) < n16;

                #define DO_ROW(BUF, D)                                              \
                {                                                                   \
                    int t  = __shfl_sync(0xffffffffu, t32, sidx + rr + (D));        \
                    int tw = (t >= 0) ? t : 0;                                      \
                    const float2* sw = (const float2*)(s_soft + tw * C);            \
                    float2 x0 = BUF[0], x1 = BUF[1], x2 = BUF[2];                   \
                    if (more) { LD3(BUF, (D) + 4) }                                 \
                    float2 w0 = sw[lane], w1 = sw[lane + 32];                       \
                    float se = __expf(x0.x) + __expf(x0.y)                          \
                             + __expf(x1.x) + __expf(x1.y);                         \
                    float dt = 0.0f;                                                \
                    dt = fmaf(w0.x, x0.x, dt); dt = fmaf(w0.y, x0.y, dt);           \
                    dt = fmaf(w1.x, x1.x, dt); dt = fmaf(w1.y, x1.y, dt);           \
                    if (act2) {                                                     \
                        float2 w2 = sw[lane + 64];                                  \
                        se += __expf(x2.x) + __expf(x2.y);                          \
                        dt = fmaf(w2.x, x2.x, dt); dt = fmaf(w2.y, x2.y, dt);       \
                    }                                                               \
                    red[(rr + (D)) * RSTR + lane] = se;                             \
                    if (t >= 0) accD -= dt;                                         \
                }

                DO_ROW(b0, 0)
                DO_ROW(b1, 1)
                DO_ROW(b2, 2)
                DO_ROW(b3, 3)
                #undef DO_ROW

                p += 4 * C2;
            }

            // batched lse: lanes 0..15 each own one row of this 16-row group
            __syncwarp();
            float sum = 0.0f;
            if (lane < 16) {
                const float4* q = (const float4*)(red + lane * RSTR);
                #pragma unroll
                for (int k = 0; k < 8; k++) {
                    float4 v = q[k];
                    sum += (v.x + v.y) + (v.z + v.w);
                }
            }
            int tr = __shfl_sync(0xffffffffu, t32, (sidx + lane) & 31);
            if (lane < 16 && tr >= 0) accL += s_ent[tr] + __logf(sum);
            __syncwarp();
        }
        #undef LD3
    }

    // scalar tail (<16 rows; empty when per-warp ranges are 16-multiples)
    for (int i = n16; i < n; i++) {
        int t = __ldg(targets + r0 + i);
        const float* lg = logits + (size_t)(r0 + i) * C;
        const float* sw = s_soft + ((t >= 0) ? t : 0) * C;
        float se = 0.f, dt = 0.f;
        for (int c = lane; c < C; c += 32) {
            float x = __ldg(lg + c);
            se += __expf(x);
            dt = fmaf(sw[c], x, dt);
        }
        se = warp_sum_f32(se);
        if (t >= 0) {
            accD -= dt;
            if (lane == 0) accL += s_ent[t] + __logf(se);
        }
    }

    block_finalize(accD + accL, lane, warp, s_w, out, B);
}

// --- generic fallback (any C, f32 table) ---------------------------------------------
__global__ __launch_bounds__(1024, 1)
void slloss_fused_gen(const float* __restrict__ logits,
                      const int*   __restrict__ targets,
                      const float* __restrict__ sim,
                      float* __restrict__ out,
                      int B, int C) {
    extern __shared__ float smemf[];
    float*  s_soft = smemf;
    float*  s_ent  = smemf + C * C;
    double* s_w    = (double*)(smemf + C * C + ((C + 1) & ~1));

    const int tid = threadIdx.x, lane = tid & 31, warp = tid >> 5;
    build_table(sim, s_soft, s_ent, C, lane, warp, (int)(blockDim.x >> 5));
    __syncthreads();

    const int NW = gridDim.x * 32;
    const int gw = blockIdx.x * 32 + warp;
    long long per = ((long long)B + NW - 1) / NW;
    long long r0 = (long long)gw * per; if (r0 > B) r0 = B;
    long long r1 = r0 + per;            if (r1 > B) r1 = B;

    float acc = 0.0f;
    for (long long row = r0; row < r1; row++) {
        int t = __ldg(&targets[row]);
        if (t < 0) continue;
        const float* lg = logits + (size_t)row * C;
        const float* sw = s_soft + t * C;
        float se = 0.f, dt = 0.f;
        for (int c = lane; c < C; c += 32) {
            float x = __ldg(lg + c);
            se += __expf(x);
            dt = fmaf(sw[c], x, dt);
        }
        se = warp_sum_f32(se);
        acc -= dt;
        if (lane == 0) acc += s_ent[t] + __logf(se);
    }
    block_finalize(acc, lane, warp, s_w, out, B);
}

extern "C" void kernel_launch(void* const* d_in, const int* in_sizes, int n_in,
                              void* d_out, int out_size) {
    const float* logits  = (const float*)d_in[0];
    const int*   targets = (const int*)  d_in[1];
    const float* sim     = (const float*)d_in[2];
    float*       out     = (float*)d_out;

    int B = in_sizes[1];
    int C = in_sizes[0] / B;

    int nsm = 148;
    cudaDeviceGetAttribute(&nsm, cudaDevAttrMultiProcessorCount, 0);

    if (C == 170) {
        constexpr int Cc = 170, W = 24, RSTR = 36;
        size_t smem = 256 + 688 + (size_t)Cc * Cc * 4 + (size_t)W * 16 * RSTR * 4;
        cudaFuncSetAttribute(slloss_v15<Cc>, cudaFuncAttributeMaxDynamicSharedMemorySize, (int)smem);
        slloss_v15<Cc><<<nsm, 768, smem>>>(logits, targets, sim, out, B);
    } else {
        size_t smem = (size_t)(C * C + ((C + 1) & ~1)) * sizeof(float) + 32 * sizeof(double);
        cudaFuncSetAttribute(slloss_fused_gen, cudaFuncAttributeMaxDynamicSharedMemorySize, (int)smem);
        slloss_fused_gen<<<nsm, 1024, smem>>>(logits, targets, sim, out, B, C);
    }
}

// round 16
// speedup vs baseline: 1.2610x; 1.0339x over previous
#include <cuda_runtime.h>
#include <math.h>

// ---------------------------------------------------------------------------
// SoftLabelLoss: loss = max( (1/B) * sum_i [ e[t_i] - dot(soft[t_i], x_i) + lse(x_i) ], 0 )
// v16 = v15 skeleton (f32 table in smem, unroll-4 register pipeline, 16-row
// batched smem lse, fixed-point finalize) with:
//   - packed f32x2 math (fma/mul/add.rn.f32x2) throughout the row body
//   - soft table stored NEGATED so the dot accumulate is one packed add
//   - 896 threads x 1 block/SM = 28 warps (73-reg budget)
// ---------------------------------------------------------------------------

#define FXSCALE 4294967296.0   // 2^32
typedef unsigned long long u64;

__device__ u64          g_sum  = 0ULL;
__device__ unsigned int g_done = 0u;

__device__ __forceinline__ float warp_sum_f32(float v) {
    #pragma unroll
    for (int o = 16; o; o >>= 1) v += __shfl_xor_sync(0xffffffffu, v, o);
    return v;
}

// --- packed f32x2 helpers -------------------------------------------------------
__device__ __forceinline__ void fma2(u64& d, u64 a, u64 b) {
    asm("fma.rn.f32x2 %0, %1, %2, %3;" : "=l"(d) : "l"(a), "l"(b), "l"(d));
}
__device__ __forceinline__ void add2(u64& d, u64 a) {
    asm("add.rn.f32x2 %0, %1, %2;" : "=l"(d) : "l"(d), "l"(a));
}
__device__ __forceinline__ u64 mul2(u64 a, u64 b) {
    u64 r; asm("mul.rn.f32x2 %0, %1, %2;" : "=l"(r) : "l"(a), "l"(b)); return r;
}
__device__ __forceinline__ void unpack2(float& lo, float& hi, u64 v) {
    asm("mov.b64 {%0, %1}, %2;" : "=f"(lo), "=f"(hi) : "l"(v));
}
__device__ __forceinline__ float ex2f(float x) {
    float r; asm("ex2.approx.ftz.f32 %0, %1;" : "=f"(r) : "f"(x)); return r;
}

// --- deterministic fixed-point finalize -------------------------------------------
__device__ __forceinline__ void block_finalize(float acc, int lane, int warp,
                                               double* s_w, float* out, int B) {
    double d = (double)acc;
    #pragma unroll
    for (int o = 16; o; o >>= 1) d += __shfl_xor_sync(0xffffffffu, d, o);
    if (lane == 0) s_w[warp] = d;
    __syncthreads();
    if (warp == 0) {
        int nw = (blockDim.x + 31) >> 5;
        double v = (lane < nw) ? s_w[lane] : 0.0;
        #pragma unroll
        for (int o = 16; o; o >>= 1) v += __shfl_xor_sync(0xffffffffu, v, o);
        if (lane == 0) {
            long long q = __double2ll_rn(v * FXSCALE);
            atomicAdd(&g_sum, (u64)q);
            __threadfence();
            unsigned int tk = atomicAdd(&g_done, 1u);
            if (tk == gridDim.x - 1) {
                u64 raw = atomicAdd(&g_sum, 0ULL);
                double loss = ((double)(long long)raw / FXSCALE) / (double)B;
                out[0] = (float)(loss > 0.0 ? loss : 0.0);
                g_sum  = 0ULL;
                g_done = 0u;
                __threadfence();
            }
        }
    }
}

// --- v16 main kernel, compile-time C (C even, 128 < C <= 172) ------------------------
template<int C>
__global__ __launch_bounds__(896, 1)
void slloss_v16(const float* __restrict__ logits,
                const int*   __restrict__ targets,
                const float* __restrict__ sim,
                float* __restrict__ out, int B) {
    constexpr int C2   = C / 2;         // 85 packed words per row
    constexpr int W    = 28;            // warps per block
    constexpr int RSTR = 36;            // se-partial row stride (floats)
    static_assert((C & 1) == 0 && C2 > 64 && C2 <= 86, "tuned for 128<C<=172");

    extern __shared__ __align__(16) unsigned char smraw[];
    double* s_w    = (double*)smraw;                              // 256 B
    float*  s_ent  = (float*)(smraw + 256);                       // C floats (pad 688)
    float*  s_soft = (float*)(smraw + 256 + 688);                 // C*C floats (NEGATED)
    float*  s_red  = (float*)(smraw + 256 + 688 + C * C * 4);     // W*16*RSTR floats

    const int lane = threadIdx.x & 31;
    const int warp = threadIdx.x >> 5;

    // ---- build NEGATED f32 table + f32 entropies ----
    for (int t = warp; t < C; t += W) {
        const float* srow = sim + (size_t)t * C;
        float s = 0.0f;
        for (int c = lane; c < C; c += 32) {
            float v = __ldg(srow + c);
            s_soft[t * C + c] = v;
            s += v;
        }
        s = warp_sum_f32(s);
        float inv = 0.2f / s;
        float pe = 0.0f;
        for (int c = lane; c < C; c += 32) {
            float soft = s_soft[t * C + c] * inv + (c == t ? 0.8f : 0.0f);
            s_soft[t * C + c] = -soft;                       // negated!
            pe += (soft > 0.0f) ? soft * __logf(soft) : 0.0f;
        }
        pe = warp_sum_f32(pe);
        if (lane == 0) s_ent[t] = pe;
    }
    __syncthreads();

    const int NW = gridDim.x * W;
    const int gw = blockIdx.x * W + warp;

    int per = (int)((((long long)B + NW - 1) / NW + 15) & ~15LL);   // mult of 16
    int r0  = gw * per;      if (r0 > B) r0 = B;
    int r1  = r0 + per;      if (r1 > B) r1 = B;
    const int n   = r1 - r0;
    const int n16 = n & ~15;

    const bool act2 = lane < (C2 - 64);       // partial third chunk (lane < 21)
    float* red = s_red + warp * (16 * RSTR);

    // log2(e) packed twice
    const unsigned ku = __float_as_uint(1.4426950408889634f);
    const u64 K2 = ((u64)ku << 32) | ku;

    u64   accD2 = 0ULL;   // packed -dot accumulator (all lanes)
    float accL  = 0.0f;   // ent + log(se) (lanes 0..15 in batched mode)

    int t32 = -1;

    if (n16 >= 16) {
        const u64* p = (const u64*)logits + (size_t)r0 * C2;

        u64 b0[3], b1[3], b2[3], b3[3];
        #define LD3(BUF, D)                                       \
            BUF[0] = __ldcs(p + (D) * C2 + lane);                 \
            BUF[1] = __ldcs(p + (D) * C2 + 32 + lane);            \
            if (act2) BUF[2] = __ldcs(p + (D) * C2 + 64 + lane);
        LD3(b0, 0) LD3(b1, 1) LD3(b2, 2) LD3(b3, 3)

        for (int i = 0; i < n16; i += 16) {
            const int gp = (i >> 4) & 1;
            if (gp == 0) {
                int rem = n - i;
                t32 = (lane < rem) ? __ldg(targets + r0 + i + lane) : -1;
            }
            const int sidx = gp << 4;

            #pragma unroll
            for (int rr = 0; rr < 16; rr += 4) {
                const bool more = (i + rr + 4) < n16;

                #define DO_ROW(BUF, D)                                              \
                {                                                                   \
                    int t  = __shfl_sync(0xffffffffu, t32, sidx + rr + (D));        \
                    int tw = (t >= 0) ? t : 0;                                      \
                    const u64* swu = (const u64*)(s_soft + tw * C);                 \
                    u64 x0 = BUF[0], x1 = BUF[1], x2 = BUF[2];                      \
                    if (more) { LD3(BUF, (D) + 4) }                                 \
                    u64 w0 = swu[lane], w1 = swu[lane + 32];                        \
                    u64 sx0 = mul2(x0, K2), sx1 = mul2(x1, K2);                     \
                    float a0, a1, a2, a3, a4, a5;                                   \
                    unpack2(a0, a1, sx0);                                           \
                    unpack2(a2, a3, sx1);                                           \
                    u64 dt2 = 0ULL;                                                 \
                    fma2(dt2, w0, x0); fma2(dt2, w1, x1);                           \
                    float se = ex2f(a0) + ex2f(a1) + ex2f(a2) + ex2f(a3);           \
                    if (act2) {                                                     \
                        u64 w2 = swu[lane + 64];                                    \
                        u64 sx2 = mul2(x2, K2);                                     \
                        unpack2(a4, a5, sx2);                                       \
                        fma2(dt2, w2, x2);                                          \
                        se += ex2f(a4) + ex2f(a5);                                  \
                    }                                                               \
                    red[(rr + (D)) * RSTR + lane] = se;                             \
                    if (t >= 0) add2(accD2, dt2);                                   \
                }

                DO_ROW(b0, 0)
                DO_ROW(b1, 1)
                DO_ROW(b2, 2)
                DO_ROW(b3, 3)
                #undef DO_ROW

                p += 4 * C2;
            }

            // batched lse: lanes 0..15 each own one row of this 16-row group
            __syncwarp();
            float sum = 0.0f;
            if (lane < 16) {
                const float4* q = (const float4*)(red + lane * RSTR);
                #pragma unroll
                for (int k = 0; k < 8; k++) {
                    float4 v = q[k];
                    sum += (v.x + v.y) + (v.z + v.w);
                }
            }
            int tr = __shfl_sync(0xffffffffu, t32, (sidx + lane) & 31);
            if (lane < 16 && tr >= 0) accL += s_ent[tr] + __logf(sum);
            __syncwarp();
        }
        #undef LD3
    }

    // scalar tail (<16 rows; empty when per-warp ranges are 16-multiples)
    float accT = 0.0f;
    for (int i = n16; i < n; i++) {
        int t = __ldg(targets + r0 + i);
        const float* lg = logits + (size_t)(r0 + i) * C;
        const float* sw = s_soft + ((t >= 0) ? t : 0) * C;   // negated weights
        float se = 0.f, dt = 0.f;
        for (int c = lane; c < C; c += 32) {
            float x = __ldg(lg + c);
            se += __expf(x);
            dt = fmaf(sw[c], x, dt);                         // accumulates -w*x
        }
        se = warp_sum_f32(se);
        if (t >= 0) {
            accT += dt;                                      // already negative
            if (lane == 0) accL += s_ent[t] + __logf(se);
        }
    }

    float dlo, dhi;
    unpack2(dlo, dhi, accD2);
    block_finalize(dlo + dhi + accT + accL, lane, warp, s_w, out, B);
}

// --- generic fallback (any C, positive f32 table) -------------------------------------
__global__ __launch_bounds__(1024, 1)
void slloss_fused_gen(const float* __restrict__ logits,
                      const int*   __restrict__ targets,
                      const float* __restrict__ sim,
                      float* __restrict__ out,
                      int B, int C) {
    extern __shared__ float smemf[];
    float*  s_soft = smemf;
    float*  s_ent  = smemf + C * C;
    double* s_w    = (double*)(smemf + C * C + ((C + 1) & ~1));

    const int tid = threadIdx.x, lane = tid & 31, warp = tid >> 5;
    for (int t = warp; t < C; t += 32) {
        const float* srow = sim + (size_t)t * C;
        float s = 0.0f;
        for (int c = lane; c < C; c += 32) {
            float v = __ldg(srow + c);
            s_soft[t * C + c] = v;
            s += v;
        }
        s = warp_sum_f32(s);
        float inv = 0.2f / s;
        float pe = 0.0f;
        for (int c = lane; c < C; c += 32) {
            float soft = s_soft[t * C + c] * inv + (c == t ? 0.8f : 0.0f);
            s_soft[t * C + c] = soft;
            pe += (soft > 0.0f) ? soft * __logf(soft) : 0.0f;
        }
        pe = warp_sum_f32(pe);
        if (lane == 0) s_ent[t] = pe;
    }
    __syncthreads();

    const int NW = gridDim.x * 32;
    const int gw = blockIdx.x * 32 + warp;
    long long per = ((long long)B + NW - 1) / NW;
    long long r0 = (long long)gw * per; if (r0 > B) r0 = B;
    long long r1 = r0 + per;            if (r1 > B) r1 = B;

    float acc = 0.0f;
    for (long long row = r0; row < r1; row++) {
        int t = __ldg(&targets[row]);
        if (t < 0) continue;
        const float* lg = logits + (size_t)row * C;
        const float* sw = s_soft + t * C;
        float se = 0.f, dt = 0.f;
        for (int c = lane; c < C; c += 32) {
            float x = __ldg(lg + c);
            se += __expf(x);
            dt = fmaf(sw[c], x, dt);
        }
        se = warp_sum_f32(se);
        acc -= dt;
        if (lane == 0) acc += s_ent[t] + __logf(se);
    }
    block_finalize(acc, lane, warp, s_w, out, B);
}

extern "C" void kernel_launch(void* const* d_in, const int* in_sizes, int n_in,
                              void* d_out, int out_size) {
    const float* logits  = (const float*)d_in[0];
    const int*   targets = (const int*)  d_in[1];
    const float* sim     = (const float*)d_in[2];
    float*       out     = (float*)d_out;

    int B = in_sizes[1];
    int C = in_sizes[0] / B;

    int nsm = 148;
    cudaDeviceGetAttribute(&nsm, cudaDevAttrMultiProcessorCount, 0);

    if (C == 170) {
        constexpr int Cc = 170, W = 28, RSTR = 36;
        size_t smem = 256 + 688 + (size_t)Cc * Cc * 4 + (size_t)W * 16 * RSTR * 4;
        cudaFuncSetAttribute(slloss_v16<Cc>, cudaFuncAttributeMaxDynamicSharedMemorySize, (int)smem);
        slloss_v16<Cc><<<nsm, 896, smem>>>(logits, targets, sim, out, B);
    } else {
        size_t smem = (size_t)(C * C + ((C + 1) & ~1)) * sizeof(float) + 32 * sizeof(double);
        cudaFuncSetAttribute(slloss_fused_gen, cudaFuncAttributeMaxDynamicSharedMemorySize, (int)smem);
        slloss_fused_gen<<<nsm, 1024, smem>>>(logits, targets, sim, out, B, C);
    }
}